// round 4
// baseline (speedup 1.0000x reference)
#include <cuda_runtime.h>
#include <cstdint>

#define BATCH 1024
#define TLEN  4096
#define DIN   8
#define PF    8        // prefetch depth (register pipeline)

// Scratch: layer-0 input gates, [t][b] layout, float4.
//   .x = 0.5*(W_r x + b_ih_r + b_hh_r)   (pre-halved for sigmoid-via-tanh)
//   .y = 0.5*(W_z x + b_ih_z + b_hh_z)
//   .z =      W_n x + b_ih_n
// Zero-padded beyond TLEN (device globals are zero-init; pad never written).
__device__ float4 g_gx[(TLEN + 2 * PF) * BATCH];

__device__ __forceinline__ float fast_tanh(float x) {
    float y; asm("tanh.approx.f32 %0, %1;" : "=f"(y) : "f"(x)); return y;
}

// Reference-order GRU cell (hidden=1), sigmoids via 0.5*tanh(a/2)+0.5.
// grh/gzh are pre-halved gate inputs (incl. both biases); gn = ff part of n.
// wrh/wzh are pre-halved recurrent weights; wn, cn unscaled.
__device__ __forceinline__ float cell(float h, float grh, float gzh, float gn,
                                      float wrh, float wzh, float wn, float cn) {
    float tr = fast_tanh(fmaf(h, wrh, grh));
    float tz = fast_tanh(fmaf(h, wzh, gzh));
    float r  = fmaf(0.5f, tr, 0.5f);
    float z  = fmaf(0.5f, tz, 0.5f);
    float n  = fast_tanh(fmaf(r, fmaf(h, wn, cn), gn));
    return fmaf(z, h - n, n);          // (1-z)n + z h
}

// ---------------------------------------------------------------------------
// Kernel 1: precompute pre-scaled layer-0 input gates.
// ---------------------------------------------------------------------------
__global__ void gx_kernel(const float* __restrict__ x,
                          const float* __restrict__ wih0,
                          const float* __restrict__ bih0,
                          const float* __restrict__ bhh0) {
    int idx = blockIdx.x * blockDim.x + threadIdx.x;
    if (idx >= BATCH * TLEN) return;
    int t = idx >> 10;          // / BATCH
    int b = idx & (BATCH - 1);  // % BATCH

    const float4* xr = reinterpret_cast<const float4*>(x + ((size_t)b * TLEN + t) * DIN);
    float4 a0 = __ldg(xr);
    float4 a1 = __ldg(xr + 1);

    float g[3];
#pragma unroll
    for (int gi = 0; gi < 3; gi++) {
        const float* w = wih0 + gi * DIN;
        float s = __ldg(bih0 + gi);
        s = fmaf(a0.x, __ldg(w + 0), s);
        s = fmaf(a0.y, __ldg(w + 1), s);
        s = fmaf(a0.z, __ldg(w + 2), s);
        s = fmaf(a0.w, __ldg(w + 3), s);
        s = fmaf(a1.x, __ldg(w + 4), s);
        s = fmaf(a1.y, __ldg(w + 5), s);
        s = fmaf(a1.z, __ldg(w + 6), s);
        s = fmaf(a1.w, __ldg(w + 7), s);
        g[gi] = s;
    }
    g_gx[idx] = make_float4(0.5f * (g[0] + __ldg(bhh0 + 0)),
                            0.5f * (g[1] + __ldg(bhh0 + 1)),
                            g[2], 0.0f);
}

// ---------------------------------------------------------------------------
// Kernel 2: sequential scan, 1 thread/batch, 3 layers time-skewed.
// Iter s: layer0@t=s, layer1@t=s-1, layer2@t=s-2. Main loop body is manually
// stage-interleaved across the 3 layers so their MUFU latencies cross-hide.
// ---------------------------------------------------------------------------
__global__ void __launch_bounds__(32, 1)
scan_kernel(const float* __restrict__ whh0, const float* __restrict__ bhh0,
            const float* __restrict__ wih1, const float* __restrict__ whh1,
            const float* __restrict__ bih1, const float* __restrict__ bhh1,
            const float* __restrict__ wih2, const float* __restrict__ whh2,
            const float* __restrict__ bih2, const float* __restrict__ bhh2,
            float* __restrict__ out) {
    int b = blockIdx.x * 32 + threadIdx.x;

    // ---- pre-scaled constants ----
    // Layer 0 recurrent (r,z halved; n unscaled)
    float w0rh = 0.5f * __ldg(whh0 + 0), w0zh = 0.5f * __ldg(whh0 + 1);
    float w0n  = __ldg(whh0 + 2),        c0n  = __ldg(bhh0 + 2);
    // Layer 1
    float u1rh = 0.5f * __ldg(wih1 + 0), u1zh = 0.5f * __ldg(wih1 + 1);
    float u1n  = __ldg(wih1 + 2);
    float d1rh = 0.5f * (__ldg(bih1 + 0) + __ldg(bhh1 + 0));
    float d1zh = 0.5f * (__ldg(bih1 + 1) + __ldg(bhh1 + 1));
    float d1n  = __ldg(bih1 + 2);
    float w1rh = 0.5f * __ldg(whh1 + 0), w1zh = 0.5f * __ldg(whh1 + 1);
    float w1n  = __ldg(whh1 + 2),        c1n  = __ldg(bhh1 + 2);
    // Layer 2
    float u2rh = 0.5f * __ldg(wih2 + 0), u2zh = 0.5f * __ldg(wih2 + 1);
    float u2n  = __ldg(wih2 + 2);
    float d2rh = 0.5f * (__ldg(bih2 + 0) + __ldg(bhh2 + 0));
    float d2zh = 0.5f * (__ldg(bih2 + 1) + __ldg(bhh2 + 1));
    float d2n  = __ldg(bih2 + 2);
    float w2rh = 0.5f * __ldg(whh2 + 0), w2zh = 0.5f * __ldg(whh2 + 1);
    float w2n  = __ldg(whh2 + 2),        c2n  = __ldg(bhh2 + 2);

    float h0, h1, h2 = 0.0f;
    float o0, o1;

    // ---- prologue s = 0: layer0 ----
    {
        float4 g = g_gx[0 * BATCH + b];
        h0 = cell(0.0f, g.x, g.y, g.z, w0rh, w0zh, w0n, c0n);
        o0 = h0;
    }
    // ---- prologue s = 1: layer0 + layer1 ----
    {
        float4 g = g_gx[1 * BATCH + b];
        float i1 = o0;
        h0 = cell(h0, g.x, g.y, g.z, w0rh, w0zh, w0n, c0n);
        h1 = cell(0.0f,
                  fmaf(i1, u1rh, d1rh), fmaf(i1, u1zh, d1zh), fmaf(i1, u1n, d1n),
                  w1rh, w1zh, w1n, c1n);
        o0 = h0; o1 = h1;
    }

    // ---- register prefetch pipeline, rows 2..2+PF-1 ----
    float4 buf[PF];
#pragma unroll
    for (int j = 0; j < PF; j++) buf[j] = g_gx[(2 + j) * BATCH + b];

    // ---- main loop s = 2 .. TLEN+1, branch-free, stage-interleaved ----
    for (int sb = 2; sb < TLEN + 2; sb += PF) {
#pragma unroll
        for (int j = 0; j < PF; j++) {
            int s = sb + j;
            float4 g = buf[j];
            buf[j] = g_gx[(s + PF) * BATCH + b];   // zero pad keeps in-bounds

            float i1 = o0, i2 = o1;

            // Stage A: r/z pre-activations, all layers (independent fmas)
            float y0r = fmaf(h0, w0rh, g.x);
            float y1r = fmaf(h1, w1rh, fmaf(i1, u1rh, d1rh));
            float y2r = fmaf(h2, w2rh, fmaf(i2, u2rh, d2rh));
            float y0z = fmaf(h0, w0zh, g.y);
            float y1z = fmaf(h1, w1zh, fmaf(i1, u1zh, d1zh));
            float y2z = fmaf(h2, w2zh, fmaf(i2, u2zh, d2zh));

            // Stage B: 6 tanh (MUFU), latencies cross-hide
            float t0r = fast_tanh(y0r);
            float t1r = fast_tanh(y1r);
            float t2r = fast_tanh(y2r);
            float t0z = fast_tanh(y0z);
            float t1z = fast_tanh(y1z);
            float t2z = fast_tanh(y2z);

            // Stage C: recurrent n parts (independent of tanh results)
            float gh0 = fmaf(h0, w0n, c0n);
            float gh1 = fmaf(h1, w1n, c1n);
            float gh2 = fmaf(h2, w2n, c2n);
            float gn1 = fmaf(i1, u1n, d1n);
            float gn2 = fmaf(i2, u2n, d2n);

            // Stage D: r gates + n pre-activations
            float r0 = fmaf(0.5f, t0r, 0.5f);
            float r1 = fmaf(0.5f, t1r, 0.5f);
            float r2 = fmaf(0.5f, t2r, 0.5f);
            float y0n = fmaf(r0, gh0, g.z);
            float y1n = fmaf(r1, gh1, gn1);
            float y2n = fmaf(r2, gh2, gn2);

            // Stage E: 3 tanh -> n
            float n0 = fast_tanh(y0n);
            float n1 = fast_tanh(y1n);
            float n2 = fast_tanh(y2n);

            // Stage F: z gates + state updates
            float z0 = fmaf(0.5f, t0z, 0.5f);
            float z1 = fmaf(0.5f, t1z, 0.5f);
            float z2 = fmaf(0.5f, t2z, 0.5f);
            h0 = fmaf(z0, h0 - n0, n0);
            h1 = fmaf(z1, h1 - n1, n1);
            h2 = fmaf(z2, h2 - n2, n2);

            o0 = h0; o1 = h1;
        }
    }
    out[b] = h2;
}

// ---------------------------------------------------------------------------
extern "C" void kernel_launch(void* const* d_in, const int* in_sizes, int n_in,
                              void* d_out, int out_size) {
    const float* x    = (const float*)d_in[0];
    const float* wih0 = (const float*)d_in[1];
    const float* whh0 = (const float*)d_in[2];
    const float* bih0 = (const float*)d_in[3];
    const float* bhh0 = (const float*)d_in[4];
    const float* wih1 = (const float*)d_in[5];
    const float* whh1 = (const float*)d_in[6];
    const float* bih1 = (const float*)d_in[7];
    const float* bhh1 = (const float*)d_in[8];
    const float* wih2 = (const float*)d_in[9];
    const float* whh2 = (const float*)d_in[10];
    const float* bih2 = (const float*)d_in[11];
    const float* bhh2 = (const float*)d_in[12];
    float* out = (float*)d_out;

    gx_kernel<<<(BATCH * TLEN + 255) / 256, 256>>>(x, wih0, bih0, bhh0);
    scan_kernel<<<BATCH / 32, 32>>>(whh0, bhh0,
                                    wih1, whh1, bih1, bhh1,
                                    wih2, whh2, bih2, bhh2, out);
}

// round 5
// speedup vs baseline: 1.6042x; 1.6042x over previous
#include <cuda_runtime.h>
#include <cstdint>

#define BATCH 1024
#define TLEN  4096
#define DIN   8
#define PF    8        // prefetch depth (register pipeline)

#define NL2E  (-1.4426950408889634f)   // -log2(e)
#define P2L2E ( 2.8853900817779268f)   //  2*log2(e)

// Layer-0 input gates, [t][b] layout, float4:
//   .x = -L2E*(W_r x + b_ih_r + b_hh_r)
//   .y = -L2E*(W_z x + b_ih_z + b_hh_z)
//   .z = 2L2E*(W_n x + b_ih_n)
// Zero-padded beyond TLEN (device globals zero-init; pad never written).
__device__ float4 g_gx[(TLEN + 2 * PF) * BATCH];

__device__ __forceinline__ float fast_ex2(float x) {
    float y; asm("ex2.approx.f32 %0, %1;" : "=f"(y) : "f"(x)); return y;
}
__device__ __forceinline__ float fast_rcp(float x) {
    float y; asm("rcp.approx.f32 %0, %1;" : "=f"(y) : "f"(x)); return y;
}

// ---------------------------------------------------------------------------
// Kernel 1: precompute pre-scaled layer-0 input gates.
// ---------------------------------------------------------------------------
__global__ void gx_kernel(const float* __restrict__ x,
                          const float* __restrict__ wih0,
                          const float* __restrict__ bih0,
                          const float* __restrict__ bhh0) {
    int idx = blockIdx.x * blockDim.x + threadIdx.x;
    if (idx >= BATCH * TLEN) return;
    int t = idx >> 10;          // / BATCH
    int b = idx & (BATCH - 1);  // % BATCH

    const float4* xr = reinterpret_cast<const float4*>(x + ((size_t)b * TLEN + t) * DIN);
    float4 a0 = __ldg(xr);
    float4 a1 = __ldg(xr + 1);

    float g[3];
#pragma unroll
    for (int gi = 0; gi < 3; gi++) {
        const float* w = wih0 + gi * DIN;
        float s = __ldg(bih0 + gi);
        s = fmaf(a0.x, __ldg(w + 0), s);
        s = fmaf(a0.y, __ldg(w + 1), s);
        s = fmaf(a0.z, __ldg(w + 2), s);
        s = fmaf(a0.w, __ldg(w + 3), s);
        s = fmaf(a1.x, __ldg(w + 4), s);
        s = fmaf(a1.y, __ldg(w + 5), s);
        s = fmaf(a1.z, __ldg(w + 6), s);
        s = fmaf(a1.w, __ldg(w + 7), s);
        g[gi] = s;
    }
    g_gx[idx] = make_float4(NL2E * (g[0] + __ldg(bhh0 + 0)),
                            NL2E * (g[1] + __ldg(bhh0 + 1)),
                            P2L2E * g[2], 0.0f);
}

// ---------------------------------------------------------------------------
// Kernel 2: systolic scan. One warp per 8 batch elements; lane = layer*8+bi.
// Skew-2: at iter s, layer l processes t = s - 2l. Cross-layer handoff via
// shfl_up(8) double-buffered one iteration ahead (keeps SHFL off the h->h
// recurrence cycle). Sigmoids via ex2+rcp (MUFU), log2e pre-folded.
// ---------------------------------------------------------------------------
__global__ void __launch_bounds__(32, 1)
scan_kernel(const float* __restrict__ whh0, const float* __restrict__ bhh0,
            const float* __restrict__ wih1, const float* __restrict__ whh1,
            const float* __restrict__ bih1, const float* __restrict__ bhh1,
            const float* __restrict__ wih2, const float* __restrict__ whh2,
            const float* __restrict__ bih2, const float* __restrict__ bhh2,
            float* __restrict__ out) {
    int lane = threadIdx.x & 31;
    int la   = lane >> 3;                 // 0,1,2 = layer; 3 = spare lanes
    int b    = blockIdx.x * 8 + (lane & 7);
    bool l0  = (la == 0);

    // Per-layer pointer tables (la==3 duplicates layer 2; results unused).
    const float* whh_a[4] = {whh0, whh1, whh2, whh2};
    const float* bhh_a[4] = {bhh0, bhh1, bhh2, bhh2};
    const float* wih_a[4] = {whh0, wih1, wih2, wih2};  // [0] is a dummy
    const float* bih_a[4] = {bhh0, bih1, bih2, bih2};  // [0] is a dummy

    const float* whh = whh_a[la];
    const float* bhh = bhh_a[la];
    const float* wih = wih_a[la];
    const float* bih = bih_a[la];

    // Recurrent constants (pre-scaled)
    float wrs = NL2E  * __ldg(whh + 0);
    float wzs = NL2E  * __ldg(whh + 1);
    float wn2 = P2L2E * __ldg(whh + 2);
    float cn2 = P2L2E * __ldg(bhh + 2);
    // Input-side constants: layer 0 passes g through (u=1, d=0).
    float urs = l0 ? 1.0f : NL2E  * __ldg(wih + 0);
    float uzs = l0 ? 1.0f : NL2E  * __ldg(wih + 1);
    float un2 = l0 ? 1.0f : P2L2E * __ldg(wih + 2);
    float drs = l0 ? 0.0f : NL2E  * (__ldg(bih + 0) + __ldg(bhh + 0));
    float dzs = l0 ? 0.0f : NL2E  * (__ldg(bih + 1) + __ldg(bhh + 1));
    float dn2 = l0 ? 0.0f : P2L2E * __ldg(bih + 2);

    float h = 0.0f;       // this lane's layer state
    float i_nx = 0.0f;    // shfl double-buffer: neighbor h, one iter ahead
    int   first_s = 2 * la;  // first iter at which this lane's update is real

    // ---- peel s = 0..3 (skew startup; updates predicated) ----
#pragma unroll
    for (int s = 0; s < 4; s++) {
        float4 g = g_gx[s * BATCH + b];
        float i = i_nx;
        i_nx = __shfl_up_sync(0xffffffffu, h, 8);
        float ir = l0 ? g.x : i;
        float iz = l0 ? g.y : i;
        float im = l0 ? g.z : i;
        float yr = fmaf(h, wrs, fmaf(ir, urs, drs));
        float yz = fmaf(h, wzs, fmaf(iz, uzs, dzs));
        float r  = fast_rcp(1.0f + fast_ex2(yr));
        float z  = fast_rcp(1.0f + fast_ex2(yz));
        float yn = fmaf(r, fmaf(h, wn2, cn2), fmaf(im, un2, dn2));
        float n  = fmaf(-2.0f, fast_rcp(1.0f + fast_ex2(yn)), 1.0f);
        float hn = fmaf(z, h - n, n);
        h = (s >= first_s) ? hn : 0.0f;
    }

    // ---- register prefetch pipeline: rows 4..4+PF-1 ----
    float4 buf[PF];
#pragma unroll
    for (int j = 0; j < PF; j++) buf[j] = g_gx[(4 + j) * BATCH + b];

    // ---- main loop: s = 4 .. TLEN+3, branch-free (4096 iters) ----
    for (int sb = 4; sb < TLEN + 4; sb += PF) {
#pragma unroll
        for (int j = 0; j < PF; j++) {
            int s = sb + j;
            float4 g = buf[j];
            buf[j] = g_gx[(s + PF) * BATCH + b];   // zero pad keeps in-bounds

            float i = i_nx;                         // neighbor h from iter s-1
            i_nx = __shfl_up_sync(0xffffffffu, h, 8);  // source ready: off-cycle

            float ir = l0 ? g.x : i;
            float iz = l0 ? g.y : i;
            float im = l0 ? g.z : i;

            float yr = fmaf(h, wrs, fmaf(ir, urs, drs));
            float yz = fmaf(h, wzs, fmaf(iz, uzs, dzs));
            float er = fast_ex2(yr);
            float ez = fast_ex2(yz);
            float r  = fast_rcp(1.0f + er);
            float z  = fast_rcp(1.0f + ez);
            float ghn2 = fmaf(h, wn2, cn2);
            float yn = fmaf(r, ghn2, fmaf(im, un2, dn2));
            float en = fast_ex2(yn);
            float q  = fast_rcp(1.0f + en);
            float n  = fmaf(-2.0f, q, 1.0f);
            h = fmaf(z, h - n, n);                  // (1-z)n + z h
        }
    }

    // Layer-2 lanes (16..23) hold h2 after t = TLEN-1 (processed at s=TLEN+3).
    if (la == 2) out[b] = h;
}

// ---------------------------------------------------------------------------
extern "C" void kernel_launch(void* const* d_in, const int* in_sizes, int n_in,
                              void* d_out, int out_size) {
    const float* x    = (const float*)d_in[0];
    const float* wih0 = (const float*)d_in[1];
    const float* whh0 = (const float*)d_in[2];
    const float* bih0 = (const float*)d_in[3];
    const float* bhh0 = (const float*)d_in[4];
    const float* wih1 = (const float*)d_in[5];
    const float* whh1 = (const float*)d_in[6];
    const float* bih1 = (const float*)d_in[7];
    const float* bhh1 = (const float*)d_in[8];
    const float* wih2 = (const float*)d_in[9];
    const float* whh2 = (const float*)d_in[10];
    const float* bih2 = (const float*)d_in[11];
    const float* bhh2 = (const float*)d_in[12];
    float* out = (float*)d_out;

    gx_kernel<<<(BATCH * TLEN + 255) / 256, 256>>>(x, wih0, bih0, bhh0);
    scan_kernel<<<BATCH / 8, 32>>>(whh0, bhh0,
                                   wih1, whh1, bih1, bhh1,
                                   wih2, whh2, bih2, bhh2, out);
}